// round 9
// baseline (speedup 1.0000x reference)
#include <cuda_runtime.h>
#include <cstdint>

// WindowOverlapProcessor: smem-staged gather with cp.async.bulk staging.
// Tile = (b, even row-pair, 256-px w slab): 66 chunks of 384B (2 contiguous
// window rows). R6 structure (one-shot 4096 blocks, 8/SM, conflict-free
// 416B chunk stride) but each chunk is ONE cp.async.bulk instead of 24
// cp.async -> staging issue cost drops 24x (LDGSTS rt=8 was the wall).
// mbarrier complete_tx synchronizes; boundary windows clamp-index+zero-weight.

#define HW_      63
#define NW_      (HW_ * HW_)
#define PLANE    (512 * 512)
#define CHUNK_F4 26                 // 24 used + 2 pad -> 416B stride
#define BUF_F4   (66 * CHUNK_F4)
#define TX_BYTES (66 * 384)

__global__ void __launch_bounds__(128, 8)
wop_bulk(const float* __restrict__ windows, float* __restrict__ out)
{
    __shared__ float4 stage[BUF_F4];          // 27456 B
    __shared__ float  g[16];
    __shared__ __align__(8) uint64_t mbar;

    int tid = threadIdx.x;
    int bx  = blockIdx.x;
    int wslab = bx & 1;
    int hpair = (bx >> 1) & 255;
    int b     = bx >> 9;
    int h0 = hpair << 1;
    int w0 = wslab << 8;

    int kh = h0 >> 3;
    int i0cl = max(kh - 1, 0), i1cl = min(kh, HW_ - 1);
    int dA = h0 - (i0cl << 3), dB = h0 - (i1cl << 3);   // even, [0,14]
    int jbase = (wslab << 5) - 1;
    int bNW = b * NW_;

    unsigned sb = (unsigned)__cvta_generic_to_shared(stage);
    unsigned mb = (unsigned)__cvta_generic_to_shared(&mbar);

    if (tid == 0)
        asm volatile("mbarrier.init.shared.b64 [%0], 1;" :: "r"(mb) : "memory");
    __syncthreads();
    if (tid == 0)
        asm volatile("mbarrier.arrive.expect_tx.shared.b64 _, [%0], %1;"
                     :: "r"(mb), "r"((unsigned)TX_BYTES) : "memory");
    __syncthreads();

    // ---- staging: 66 bulk copies of 384B each ----
    if (tid < 66) {
        int ii = (tid >= 33);
        int u  = ii ? tid - 33 : tid;
        int j  = min(max(jbase + u, 0), HW_ - 1);
        int iw = ii ? i1cl : i0cl;
        int dd = ii ? dB : dA;
        const float* src = windows + (bNW + iw * HW_ + j) * 768 + dd * 48;
        unsigned dst = sb + (unsigned)tid * (CHUNK_F4 * 16);
        asm volatile(
            "cp.async.bulk.shared::cta.global.mbarrier::complete_tx::bytes "
            "[%0], [%1], %2, [%3];"
            :: "r"(dst), "l"(src), "r"(384), "r"(mb) : "memory");
    }

    // ---- gaussian table (overlaps the bulk copies) ----
    if (tid < 16) { float x = (float)tid - 7.5f; g[tid] = expf(-(x * x) / 32.0f); }
    __syncthreads();
    if (tid == 0) {
        float ssum = 0.0f;
        #pragma unroll
        for (int k = 0; k < 16; k++) ssum += g[k];
        float si = 1.0f / ssum;
        #pragma unroll
        for (int k = 0; k < 16; k++) g[k] *= si;
    }
    __syncthreads();

    // ---- wait for staged data (acquire orders the LDS reads below) ----
    {
        unsigned done;
        asm volatile(
            "{\n\t.reg .pred p;\n\t"
            "mbarrier.try_wait.parity.acquire.cta.shared::cta.b64 p, [%1], 0;\n\t"
            "selp.b32 %0, 1, 0, p;\n\t}"
            : "=r"(done) : "r"(mb) : "memory");
        if (!done) {
            asm volatile(
                "{\n\t.reg .pred P1;\n\t"
                "WL_%=:\n\t"
                "mbarrier.try_wait.parity.acquire.cta.shared::cta.b64 P1, [%0], 0, 0x989680;\n\t"
                "@P1 bra.uni WD_%=;\n\t"
                "bra.uni WL_%=;\n\t"
                "WD_%=:\n\t}"
                :: "r"(mb) : "memory");
        }
    }

    // ---- consumer: thread = (row r, w4 group) ----
    int r     = tid >> 6;
    int w4loc = (tid & 63) << 2;
    int w4 = w0 + w4loc;
    int h  = h0 + r;
    int kw = w4 >> 3;
    int u0 = w4loc >> 3;
    int dwA = (w4 & 7) + 8;            // {8,12}  window kw-1
    int dwB = w4 & 7;                  // {0,4}   window kw

    bool vi0 = (kh >= 1),  vi1 = (kh <= HW_ - 1);
    bool vj0 = (kw >= 1),  vj1 = (kw <= HW_ - 1);

    float gh0 = vi0 ? g[(h & 7) + 8] : 0.0f;
    float gh1 = vi1 ? g[h & 7]       : 0.0f;
    float gwA0 = vj0 ? g[dwA]     : 0.0f;
    float gwA1 = vj0 ? g[dwA + 1] : 0.0f;
    float gwA2 = vj0 ? g[dwA + 2] : 0.0f;
    float gwA3 = vj0 ? g[dwA + 3] : 0.0f;
    float gwB0 = vj1 ? g[dwB]     : 0.0f;
    float gwB1 = vj1 ? g[dwB + 1] : 0.0f;
    float gwB2 = vj1 ? g[dwB + 2] : 0.0f;
    float gwB3 = vj1 ? g[dwB + 3] : 0.0f;

    float sh = gh0 + gh1;
    float inv0 = 1.0f / (sh * (gwA0 + gwB0) + 1e-8f);
    float inv1 = 1.0f / (sh * (gwA1 + gwB1) + 1e-8f);
    float inv2 = 1.0f / (sh * (gwA2 + gwB2) + 1e-8f);
    float inv3 = 1.0f / (sh * (gwA3 + gwB3) + 1e-8f);

    int rowoff = r * 12;
    int fA = (dwA * 3) >> 2;           // 6 or 9
    int fB = (dwB * 3) >> 2;           // 0 or 3
    int c00 = (u0)      * CHUNK_F4 + rowoff + fA;
    int c01 = (u0 + 1)  * CHUNK_F4 + rowoff + fB;
    int c10 = (33 + u0) * CHUNK_F4 + rowoff + fA;
    int c11 = (34 + u0) * CHUNK_F4 + rowoff + fB;

    float a00, a01, a02, a10, a11, a12, a20, a21, a22, a30, a31, a32;
    // per 3-float4 group: va={p0c0,p0c1,p0c2,p1c0} vb={p1c1,p1c2,p2c0,p2c1}
    //                     vc={p2c2,p3c0,p3c1,p3c2}
    {
        float4 va = stage[c00], vb = stage[c00 + 1], vc = stage[c00 + 2];
        float q0 = gh0 * gwA0, q1 = gh0 * gwA1, q2 = gh0 * gwA2, q3 = gh0 * gwA3;
        a00 = q0 * va.x; a01 = q0 * va.y; a02 = q0 * va.z;
        a10 = q1 * va.w; a11 = q1 * vb.x; a12 = q1 * vb.y;
        a20 = q2 * vb.z; a21 = q2 * vb.w; a22 = q2 * vc.x;
        a30 = q3 * vc.y; a31 = q3 * vc.z; a32 = q3 * vc.w;
    }
    {
        float4 va = stage[c01], vb = stage[c01 + 1], vc = stage[c01 + 2];
        float q0 = gh0 * gwB0, q1 = gh0 * gwB1, q2 = gh0 * gwB2, q3 = gh0 * gwB3;
        a00 += q0 * va.x; a01 += q0 * va.y; a02 += q0 * va.z;
        a10 += q1 * va.w; a11 += q1 * vb.x; a12 += q1 * vb.y;
        a20 += q2 * vb.z; a21 += q2 * vb.w; a22 += q2 * vc.x;
        a30 += q3 * vc.y; a31 += q3 * vc.z; a32 += q3 * vc.w;
    }
    {
        float4 va = stage[c10], vb = stage[c10 + 1], vc = stage[c10 + 2];
        float q0 = gh1 * gwA0, q1 = gh1 * gwA1, q2 = gh1 * gwA2, q3 = gh1 * gwA3;
        a00 += q0 * va.x; a01 += q0 * va.y; a02 += q0 * va.z;
        a10 += q1 * va.w; a11 += q1 * vb.x; a12 += q1 * vb.y;
        a20 += q2 * vb.z; a21 += q2 * vb.w; a22 += q2 * vc.x;
        a30 += q3 * vc.y; a31 += q3 * vc.z; a32 += q3 * vc.w;
    }
    {
        float4 va = stage[c11], vb = stage[c11 + 1], vc = stage[c11 + 2];
        float q0 = gh1 * gwB0, q1 = gh1 * gwB1, q2 = gh1 * gwB2, q3 = gh1 * gwB3;
        a00 += q0 * va.x; a01 += q0 * va.y; a02 += q0 * va.z;
        a10 += q1 * va.w; a11 += q1 * vb.x; a12 += q1 * vb.y;
        a20 += q2 * vb.z; a21 += q2 * vb.w; a22 += q2 * vc.x;
        a30 += q3 * vc.y; a31 += q3 * vc.z; a32 += q3 * vc.w;
    }

    float* ob = out + b * (3 * PLANE) + (h << 9) + w4;
    *(float4*)(ob)             = make_float4(a00 * inv0, a10 * inv1, a20 * inv2, a30 * inv3);
    *(float4*)(ob + PLANE)     = make_float4(a01 * inv0, a11 * inv1, a21 * inv2, a31 * inv3);
    *(float4*)(ob + 2 * PLANE) = make_float4(a02 * inv0, a12 * inv1, a22 * inv2, a32 * inv3);
}

extern "C" void kernel_launch(void* const* d_in, const int* in_sizes, int n_in,
                              void* d_out, int out_size)
{
    const float* windows = (const float*)d_in[0];
    float* out = (float*)d_out;
    cudaFuncSetAttribute(wop_bulk, cudaFuncAttributePreferredSharedMemoryCarveout, 100);
    // 8 b x 256 h-pairs x 2 w-slabs = 4096 one-shot blocks
    wop_bulk<<<4096, 128>>>(windows, out);
}

// round 10
// speedup vs baseline: 1.2058x; 1.2058x over previous
#include <cuda_runtime.h>

// WindowOverlapProcessor: R6 structure (best so far), overheads removed.
// Tile = (b, even row-pair, 256-px w slab): 66 chunks x 384B staged via
// cp.async (conflict-free 416B chunk stride), one-shot 4096 blocks, 8/SM.
// Changes vs R6: gaussian table is compile-time (normalization folded into
// eps' = 1e-8*s^2), weight lookups are FSELs between immediates -> no expf,
// no table smem, 1 barrier per tile instead of 4. Output stored with __stcs
// (evict-first) to keep the windows tensor L2-resident across graph replays.

#define HW_      63
#define NW_      (HW_ * HW_)
#define PLANE    (512 * 512)
#define CHUNK_F4 26
#define BUF_F4   (66 * CHUNK_F4)

// raw (unnormalized) gaussian g[k] = exp(-(k-7.5)^2/32); s = sum = 9.57593628
#define G0 0.17242162f
#define G1 0.26705262f
#define G2 0.38855860f
#define G3 0.53109700f
#define G4 0.68194030f
#define G5 0.82257760f
#define G6 0.93210250f
#define G7 0.99221790f
#define EPS2 9.1698556e-7f          // 1e-8 * s^2

__constant__ float GT[16] = { G0, G1, G2, G3, G4, G5, G6, G7,
                              G7, G6, G5, G4, G3, G2, G1, G0 };

__global__ void __launch_bounds__(128, 8)
wop_r10(const float* __restrict__ windows, float* __restrict__ out)
{
    __shared__ float4 stage[BUF_F4];          // 27456 B

    int tid = threadIdx.x;
    int bx  = blockIdx.x;
    int wslab = bx & 1;
    int hpair = (bx >> 1) & 255;
    int b     = bx >> 9;
    int h0 = hpair << 1;
    int w0 = wslab << 8;

    int kh = h0 >> 3;
    int i0cl = max(kh - 1, 0), i1cl = min(kh, HW_ - 1);
    int dA = h0 - (i0cl << 3), dB = h0 - (i1cl << 3);   // even, [0,14]
    int jbase = (wslab << 5) - 1;
    int bNW = b * NW_;

    unsigned sb = (unsigned)__cvta_generic_to_shared(stage);

    // ---- staging: 66 chunks x 24 float4 via cp.async (R6 scheme) ----
    {
        int base0 = (bNW + i0cl * HW_) * 192 + dA * 12;   // float4 units
        int base1 = (bNW + i1cl * HW_) * 192 + dB * 12;

        int c = tid / 24, w = tid - c * 24;
        #pragma unroll 1
        for (int s = tid; s < 792; s += 128) {
            int j = min(max(jbase + c, 0), HW_ - 1);
            const float4* src = ((const float4*)windows) + (base0 + j * 192 + w);
            unsigned dst = sb + (unsigned)((c * CHUNK_F4 + w) << 4);
            asm volatile("cp.async.cg.shared.global [%0], [%1], 16;"
                         :: "r"(dst), "l"(src) : "memory");
            w += 8; c += 5; if (w >= 24) { w -= 24; ++c; }
        }
        c = tid / 24; w = tid - c * 24;
        #pragma unroll 1
        for (int s = tid; s < 792; s += 128) {
            int j = min(max(jbase + c, 0), HW_ - 1);
            const float4* src = ((const float4*)windows) + (base1 + j * 192 + w);
            unsigned dst = sb + (unsigned)(((33 + c) * CHUNK_F4 + w) << 4);
            asm volatile("cp.async.cg.shared.global [%0], [%1], 16;"
                         :: "r"(dst), "l"(src) : "memory");
            w += 8; c += 5; if (w >= 24) { w -= 24; ++c; }
        }
        asm volatile("cp.async.commit_group;" ::: "memory");
    }

    // ---- consumer setup (overlaps the copies; no table build needed) ----
    int r     = tid >> 6;
    int w4loc = (tid & 63) << 2;
    int w4 = w0 + w4loc;
    int h  = h0 + r;
    int kw = w4 >> 3;
    int u0 = w4loc >> 3;
    bool selhi = (w4 & 4) != 0;        // dwA=12 / dwB=4 when set

    bool vi0 = (kh >= 1),  vi1 = (kh <= HW_ - 1);
    bool vj0 = (kw >= 1),  vj1 = (kw <= HW_ - 1);

    float gh0 = vi0 ? GT[(h & 7) + 8] : 0.0f;   // uniform per warp -> LDCU
    float gh1 = vi1 ? GT[h & 7]       : 0.0f;

    // window kw-1 quad: dwA=8 -> {G7r..}=GT[8..11]; dwA=12 -> GT[12..15]
    float gwA0 = vj0 ? (selhi ? G3 : G7) : 0.0f;
    float gwA1 = vj0 ? (selhi ? G2 : G6) : 0.0f;
    float gwA2 = vj0 ? (selhi ? G1 : G5) : 0.0f;
    float gwA3 = vj0 ? (selhi ? G0 : G4) : 0.0f;
    // window kw quad: dwB=0 -> GT[0..3]; dwB=4 -> GT[4..7]
    float gwB0 = vj1 ? (selhi ? G4 : G0) : 0.0f;
    float gwB1 = vj1 ? (selhi ? G5 : G1) : 0.0f;
    float gwB2 = vj1 ? (selhi ? G6 : G2) : 0.0f;
    float gwB3 = vj1 ? (selhi ? G7 : G3) : 0.0f;

    float sh = gh0 + gh1;
    float inv0 = 1.0f / (sh * (gwA0 + gwB0) + EPS2);
    float inv1 = 1.0f / (sh * (gwA1 + gwB1) + EPS2);
    float inv2 = 1.0f / (sh * (gwA2 + gwB2) + EPS2);
    float inv3 = 1.0f / (sh * (gwA3 + gwB3) + EPS2);

    int rowoff = r * 12;
    int fA = selhi ? 9 : 6;            // (dwA*3)>>2
    int fB = selhi ? 3 : 0;            // (dwB*3)>>2
    int c00 = (u0)      * CHUNK_F4 + rowoff + fA;
    int c01 = (u0 + 1)  * CHUNK_F4 + rowoff + fB;
    int c10 = (33 + u0) * CHUNK_F4 + rowoff + fA;
    int c11 = (34 + u0) * CHUNK_F4 + rowoff + fB;

    asm volatile("cp.async.wait_group 0;" ::: "memory");
    __syncthreads();                   // staged data visible to all warps

    float a00, a01, a02, a10, a11, a12, a20, a21, a22, a30, a31, a32;
    // per 3-float4 group: va={p0c0,p0c1,p0c2,p1c0} vb={p1c1,p1c2,p2c0,p2c1}
    //                     vc={p2c2,p3c0,p3c1,p3c2}
    {
        float4 va = stage[c00], vb = stage[c00 + 1], vc = stage[c00 + 2];
        float q0 = gh0 * gwA0, q1 = gh0 * gwA1, q2 = gh0 * gwA2, q3 = gh0 * gwA3;
        a00 = q0 * va.x; a01 = q0 * va.y; a02 = q0 * va.z;
        a10 = q1 * va.w; a11 = q1 * vb.x; a12 = q1 * vb.y;
        a20 = q2 * vb.z; a21 = q2 * vb.w; a22 = q2 * vc.x;
        a30 = q3 * vc.y; a31 = q3 * vc.z; a32 = q3 * vc.w;
    }
    {
        float4 va = stage[c01], vb = stage[c01 + 1], vc = stage[c01 + 2];
        float q0 = gh0 * gwB0, q1 = gh0 * gwB1, q2 = gh0 * gwB2, q3 = gh0 * gwB3;
        a00 += q0 * va.x; a01 += q0 * va.y; a02 += q0 * va.z;
        a10 += q1 * va.w; a11 += q1 * vb.x; a12 += q1 * vb.y;
        a20 += q2 * vb.z; a21 += q2 * vb.w; a22 += q2 * vc.x;
        a30 += q3 * vc.y; a31 += q3 * vc.z; a32 += q3 * vc.w;
    }
    {
        float4 va = stage[c10], vb = stage[c10 + 1], vc = stage[c10 + 2];
        float q0 = gh1 * gwA0, q1 = gh1 * gwA1, q2 = gh1 * gwA2, q3 = gh1 * gwA3;
        a00 += q0 * va.x; a01 += q0 * va.y; a02 += q0 * va.z;
        a10 += q1 * va.w; a11 += q1 * vb.x; a12 += q1 * vb.y;
        a20 += q2 * vb.z; a21 += q2 * vb.w; a22 += q2 * vc.x;
        a30 += q3 * vc.y; a31 += q3 * vc.z; a32 += q3 * vc.w;
    }
    {
        float4 va = stage[c11], vb = stage[c11 + 1], vc = stage[c11 + 2];
        float q0 = gh1 * gwB0, q1 = gh1 * gwB1, q2 = gh1 * gwB2, q3 = gh1 * gwB3;
        a00 += q0 * va.x; a01 += q0 * va.y; a02 += q0 * va.z;
        a10 += q1 * va.w; a11 += q1 * vb.x; a12 += q1 * vb.y;
        a20 += q2 * vb.z; a21 += q2 * vb.w; a22 += q2 * vc.x;
        a30 += q3 * vc.y; a31 += q3 * vc.z; a32 += q3 * vc.w;
    }

    float* ob = out + b * (3 * PLANE) + (h << 9) + w4;
    __stcs((float4*)(ob),
           make_float4(a00 * inv0, a10 * inv1, a20 * inv2, a30 * inv3));
    __stcs((float4*)(ob + PLANE),
           make_float4(a01 * inv0, a11 * inv1, a21 * inv2, a31 * inv3));
    __stcs((float4*)(ob + 2 * PLANE),
           make_float4(a02 * inv0, a12 * inv1, a22 * inv2, a32 * inv3));
}

extern "C" void kernel_launch(void* const* d_in, const int* in_sizes, int n_in,
                              void* d_out, int out_size)
{
    const float* windows = (const float*)d_in[0];
    float* out = (float*)d_out;
    cudaFuncSetAttribute(wop_r10, cudaFuncAttributePreferredSharedMemoryCarveout, 100);
    // 8 b x 256 h-pairs x 2 w-slabs = 4096 one-shot blocks
    wop_r10<<<4096, 128>>>(windows, out);
}